// round 3
// baseline (speedup 1.0000x reference)
#include <cuda_runtime.h>
#include <cstdint>

// Problem constants
#define TB 16   // batch
#define TH 8    // heads
#define TL 128  // seq len
#define TD 64   // head dim

// Output layout: [output (B,H,B,L,D)] then [attn_weights (B,H,B,L,L)]
constexpr long long OUT_ATTN_OFF = (long long)TB * TH * TB * TL * TD; // 16,777,216

// Shared memory layout (floats):
//   region0 [0, 128*132): Qt (k-major, 64x128) at [0,8192), Kt at [8448,16640)
//                          later reused as S[128][SLD]
//   Vs at [16896, 16896+8192): V row-major [128][64]
constexpr int SLD      = 132;            // S row stride (bank-conflict + 16B-align friendly)
constexpr int KT_OFF   = 8448;
constexpr int V_OFF    = 16896;          // = 128*132
constexpr int SMEM_FLOATS = V_OFF + TL * TD;     // 25088
constexpr int SMEM_BYTES  = SMEM_FLOATS * 4;     // 100,352 B -> 2 CTAs/SM

// ---- packed f32x2 helpers (Blackwell) ----
__device__ __forceinline__ uint64_t splat2(float x) {
    uint64_t r;
    asm("mov.b64 %0, {%1, %1};" : "=l"(r) : "f"(x));
    return r;
}
__device__ __forceinline__ void fma2(uint64_t& d, uint64_t a, uint64_t b) {
    asm("fma.rn.f32x2 %0, %1, %2, %0;" : "+l"(d) : "l"(a), "l"(b));
}
__device__ __forceinline__ float2 unpack2(uint64_t v) {
    float2 r;
    asm("mov.b64 {%0, %1}, %2;" : "=f"(r.x), "=f"(r.y) : "l"(v));
    return r;
}

__global__ __launch_bounds__(256, 2)
void isa_kernel(const float* __restrict__ Q, const float* __restrict__ K,
                const float* __restrict__ V, const int* __restrict__ Mask,
                float* __restrict__ out)
{
    extern __shared__ float sm[];
    float* Qt = sm;              // [64][128] k-major
    float* Kt = sm + KT_OFF;     // [64][128] k-major
    float* S  = sm;              // [128][SLD], reuses Qt/Kt region after GEMM1
    float* Vs = sm + V_OFF;      // [128][64] row-major

    const int tid = threadIdx.x;
    const int cta = blockIdx.x;          // cta = ((b*TH + h)*TB + c)
    const int c = cta & 15;
    const int h = (cta >> 4) & 7;
    const int b = cta >> 7;

    const float4* Q4 = (const float4*)(Q + (size_t)((b * TH + h) * TL) * TD);
    const float4* K4 = (const float4*)(K + (size_t)((h * TB + c) * TL) * TD);
    const float4* V4 = (const float4*)(V + (size_t)((h * TB + c) * TL) * TD);
    const int*    Mg = Mask + (size_t)b * TL * TL;

    // ---- Stage tiles: Q,K transposed to k-major; V row-major ----
    {
        float4* Vs4 = (float4*)Vs;
        #pragma unroll
        for (int it = 0; it < 8; it++) {
            int idx = tid + it * 256;                 // 2048 float4s per tile
            int i  = idx >> 4;                        // row (coalesced in gmem)
            int kg = (idx & 15) << 2;                 // k group of 4
            float4 q = Q4[idx];
            Qt[(kg + 0) * 128 + i] = q.x;
            Qt[(kg + 1) * 128 + i] = q.y;
            Qt[(kg + 2) * 128 + i] = q.z;
            Qt[(kg + 3) * 128 + i] = q.w;
            float4 kk = K4[idx];
            Kt[(kg + 0) * 128 + i] = kk.x;
            Kt[(kg + 1) * 128 + i] = kk.y;
            Kt[(kg + 2) * 128 + i] = kk.z;
            Kt[(kg + 3) * 128 + i] = kk.w;
            Vs4[idx] = V4[idx];
        }
    }
    __syncthreads();

    // ---- GEMM1: S = Q @ K^T  (128x128x64), f32x2-packed along rows ----
    const int tx = tid & 15;     // col group
    const int ty = tid >> 4;     // row group
    const int ri = ty * 8;
    const int cj = tx * 8;

    uint64_t acc[4][8];
    #pragma unroll
    for (int r = 0; r < 4; r++)
        #pragma unroll
        for (int cc = 0; cc < 8; cc++) acc[r][cc] = 0ull;

    #pragma unroll 2
    for (int k = 0; k < TD; k++) {
        const float* qr = &Qt[k * 128 + ri];
        ulonglong2 a01 = *(const ulonglong2*)(qr);       // rows (ri,ri+1),(ri+2,ri+3)
        ulonglong2 a23 = *(const ulonglong2*)(qr + 4);   // rows (ri+4..ri+7)
        uint64_t a2[4] = { a01.x, a01.y, a23.x, a23.y };
        float4 b0 = *(const float4*)&Kt[k * 128 + cj];
        float4 b1 = *(const float4*)&Kt[k * 128 + cj + 4];
        uint64_t bs[8] = { splat2(b0.x), splat2(b0.y), splat2(b0.z), splat2(b0.w),
                           splat2(b1.x), splat2(b1.y), splat2(b1.z), splat2(b1.w) };
        #pragma unroll
        for (int r = 0; r < 4; r++)
            #pragma unroll
            for (int cc = 0; cc < 8; cc++)
                fma2(acc[r][cc], a2[r], bs[cc]);
    }
    __syncthreads();   // done reading Qt/Kt; region becomes S

    #pragma unroll
    for (int r = 0; r < 4; r++) {
        int row0 = ri + 2 * r;
        #pragma unroll
        for (int cc = 0; cc < 8; cc++) {
            float2 v = unpack2(acc[r][cc]);
            S[row0 * SLD + cj + cc]       = v.x;
            S[(row0 + 1) * SLD + cj + cc] = v.y;
        }
    }
    __syncthreads();

    // ---- Masked softmax, one warp per row; writes attn_weights + P into S ----
    {
        const int wid  = tid >> 5;
        const int lane = tid & 31;
        float* attn = out + OUT_ATTN_OFF + (long long)cta * (TL * TL);
        for (int row = wid; row < TL; row += 8) {
            float s[4];
            #pragma unroll
            for (int u = 0; u < 4; u++) {
                int j = lane + 32 * u;
                float v = S[row * SLD + j] * 0.125f;      // / sqrt(64)
                if (Mg[row * 128 + j] == 0) v = -1e9f;
                s[u] = v;
            }
            float m = fmaxf(fmaxf(s[0], s[1]), fmaxf(s[2], s[3]));
            #pragma unroll
            for (int o = 16; o > 0; o >>= 1)
                m = fmaxf(m, __shfl_xor_sync(0xffffffffu, m, o));
            float p[4], sum = 0.f;
            #pragma unroll
            for (int u = 0; u < 4; u++) { p[u] = __expf(s[u] - m); sum += p[u]; }
            #pragma unroll
            for (int o = 16; o > 0; o >>= 1)
                sum += __shfl_xor_sync(0xffffffffu, sum, o);
            float inv = 1.0f / sum;
            #pragma unroll
            for (int u = 0; u < 4; u++) {
                int j = lane + 32 * u;
                float w = p[u] * inv;
                S[row * SLD + j] = w;
                attn[row * 128 + j] = w;
            }
        }
    }
    __syncthreads();

    // ---- GEMM2: O = P @ V  (128x64x128), f32x2-packed along cols ----
    {
        const int tx2 = tid & 7;
        const int ty2 = tid >> 3;
        const int r0 = ty2 * 4;
        const int c0 = tx2 * 8;

        uint64_t oacc[4][4];
        #pragma unroll
        for (int r = 0; r < 4; r++)
            #pragma unroll
            for (int cc = 0; cc < 4; cc++) oacc[r][cc] = 0ull;

        #pragma unroll 2
        for (int j = 0; j < TL; j++) {
            ulonglong2 v0 = *(const ulonglong2*)&Vs[j * 64 + c0];
            ulonglong2 v1 = *(const ulonglong2*)&Vs[j * 64 + c0 + 4];
            uint64_t bv[4] = { v0.x, v0.y, v1.x, v1.y };
            #pragma unroll
            for (int r = 0; r < 4; r++) {
                uint64_t a = splat2(S[(r0 + r) * SLD + j]);
                #pragma unroll
                for (int cc = 0; cc < 4; cc++)
                    fma2(oacc[r][cc], a, bv[cc]);
            }
        }

        float* og = out + (long long)cta * (TL * TD);
        #pragma unroll
        for (int r = 0; r < 4; r++) {
            float2 p0 = unpack2(oacc[r][0]);
            float2 p1 = unpack2(oacc[r][1]);
            float2 p2 = unpack2(oacc[r][2]);
            float2 p3 = unpack2(oacc[r][3]);
            float4 w0 = make_float4(p0.x, p0.y, p1.x, p1.y);
            float4 w1 = make_float4(p2.x, p2.y, p3.x, p3.y);
            *(float4*)&og[(r0 + r) * 64 + c0]     = w0;
            *(float4*)&og[(r0 + r) * 64 + c0 + 4] = w1;
        }
    }
}

extern "C" void kernel_launch(void* const* d_in, const int* in_sizes, int n_in,
                              void* d_out, int out_size)
{
    const float* Q  = (const float*)d_in[0];
    const float* K  = (const float*)d_in[1];
    const float* V  = (const float*)d_in[2];
    const int*   Mk = (const int*)d_in[3];
    float* out = (float*)d_out;

    // >48KB dynamic smem opt-in (host-side attribute set; capture-safe, idempotent)
    cudaFuncSetAttribute(isa_kernel, cudaFuncAttributeMaxDynamicSharedMemorySize, SMEM_BYTES);

    isa_kernel<<<TB * TH * TB, 256, SMEM_BYTES>>>(Q, K, V, Mk, out);
}

// round 7
// speedup vs baseline: 2.9891x; 2.9891x over previous
#include <cuda_runtime.h>
#include <cuda_bf16.h>
#include <cstdint>

// Problem constants
#define TB 16   // batch
#define TH 8    // heads
#define TL 128  // seq len
#define TD 64   // head dim

constexpr long long OUT_ATTN_OFF = (long long)TB * TH * TB * TL * TD; // 16,777,216

// ---------------- shared memory layout (bytes) ----------------
// Q/K/V tiles: bf16 rows padded to 144B (stride = 4 banks mod 32 -> conflict-free ldmatrix)
constexpr int QK_STRIDE = 144;     // 64 bf16 = 128B data + 16B pad
constexpr int P_STRIDE  = 272;     // 128 bf16 = 256B data + 16B pad
constexpr int OFF_QH = 0;
constexpr int OFF_QL = OFF_QH + 128 * QK_STRIDE;   // 18432
constexpr int OFF_KH = OFF_QL + 128 * QK_STRIDE;   // 36864
constexpr int OFF_KL = OFF_KH + 128 * QK_STRIDE;   // 55296
constexpr int OFF_VH = OFF_KL + 128 * QK_STRIDE;   // 73728
constexpr int OFF_VL = OFF_VH + 128 * QK_STRIDE;   // 92160
constexpr int SMEM_BYTES = OFF_VL + 128 * QK_STRIDE; // 110592 -> 2 CTAs/SM
// P (bf16 hi/lo, 128x128) overlays Q/K region after GEMM1 (barrier-protected)
constexpr int OFF_PH = 0;
constexpr int OFF_PL = OFF_PH + 128 * P_STRIDE;    // 34816 (ends 69632 < OFF_VH)

// ---------------- PTX helpers ----------------
__device__ __forceinline__ uint32_t smem_u32(const void* p) {
    uint32_t a;
    asm("{ .reg .u64 t; cvta.to.shared.u64 t, %1; cvt.u32.u64 %0, t; }" : "=r"(a) : "l"(p));
    return a;
}
__device__ __forceinline__ void ldsm_x4(uint32_t* r, uint32_t addr) {
    asm volatile("ldmatrix.sync.aligned.m8n8.x4.shared.b16 {%0,%1,%2,%3}, [%4];"
        : "=r"(r[0]), "=r"(r[1]), "=r"(r[2]), "=r"(r[3]) : "r"(addr));
}
__device__ __forceinline__ void ldsm_x2(uint32_t* r, uint32_t addr) {
    asm volatile("ldmatrix.sync.aligned.m8n8.x2.shared.b16 {%0,%1}, [%2];"
        : "=r"(r[0]), "=r"(r[1]) : "r"(addr));
}
__device__ __forceinline__ void ldsm_x2t(uint32_t* r, uint32_t addr) {
    asm volatile("ldmatrix.sync.aligned.m8n8.x2.trans.shared.b16 {%0,%1}, [%2];"
        : "=r"(r[0]), "=r"(r[1]) : "r"(addr));
}
// D += A * B   (m16n8k16, bf16 in, fp32 accum)
__device__ __forceinline__ void mma_bf16(float* c, const uint32_t* a, const uint32_t* b) {
    asm volatile("mma.sync.aligned.m16n8k16.row.col.f32.bf16.bf16.f32 "
        "{%0,%1,%2,%3}, {%4,%5,%6,%7}, {%8,%9}, {%0,%1,%2,%3};"
        : "+f"(c[0]), "+f"(c[1]), "+f"(c[2]), "+f"(c[3])
        : "r"(a[0]), "r"(a[1]), "r"(a[2]), "r"(a[3]), "r"(b[0]), "r"(b[1]));
}
// pack two floats -> bf16x2 (x in low half, y in high half)
__device__ __forceinline__ uint32_t pack_bf2(float x, float y) {
    uint32_t r;
    asm("cvt.rn.bf16x2.f32 %0, %1, %2;" : "=r"(r) : "f"(y), "f"(x));
    return r;
}
__device__ __forceinline__ float bf_hi_f(float x) {   // value of bf16(x) as float
    return __bfloat162float(__float2bfloat16(x));
}

__global__ __launch_bounds__(256, 2)
void isa_hmma_kernel(const float* __restrict__ Q, const float* __restrict__ K,
                     const float* __restrict__ V, const int* __restrict__ Mask,
                     float* __restrict__ out)
{
    extern __shared__ char smc[];
    const uint32_t sb = smem_u32(smc);
    const int tid  = threadIdx.x;
    const int wid  = tid >> 5;
    const int lane = tid & 31;

    const int cta = blockIdx.x;          // ((b*TH + h)*TB + c)
    const int c = cta & 15;
    const int h = (cta >> 4) & 7;
    const int b = cta >> 7;

    const float4* Q4 = (const float4*)(Q + (size_t)((b * TH + h) * TL) * TD);
    const float4* K4 = (const float4*)(K + (size_t)((h * TB + c) * TL) * TD);
    const float4* V4 = (const float4*)(V + (size_t)((h * TB + c) * TL) * TD);

    // ---- stage Q,K,V -> bf16 hi/lo rows (144B stride) ----
    #pragma unroll
    for (int it = 0; it < 8; it++) {
        int idx = tid + it * 256;            // 2048 float4 per tensor
        int r   = idx >> 4;                  // row
        int c4  = (idx & 15) << 2;           // col group of 4
        uint32_t boff = (uint32_t)(r * QK_STRIDE + c4 * 2);

        float4 q = Q4[idx];
        float qhx = bf_hi_f(q.x), qhy = bf_hi_f(q.y), qhz = bf_hi_f(q.z), qhw = bf_hi_f(q.w);
        *(uint2*)(smc + OFF_QH + boff) = make_uint2(pack_bf2(q.x, q.y), pack_bf2(q.z, q.w));
        *(uint2*)(smc + OFF_QL + boff) = make_uint2(pack_bf2(q.x - qhx, q.y - qhy),
                                                    pack_bf2(q.z - qhz, q.w - qhw));
        float4 kk = K4[idx];
        float khx = bf_hi_f(kk.x), khy = bf_hi_f(kk.y), khz = bf_hi_f(kk.z), khw = bf_hi_f(kk.w);
        *(uint2*)(smc + OFF_KH + boff) = make_uint2(pack_bf2(kk.x, kk.y), pack_bf2(kk.z, kk.w));
        *(uint2*)(smc + OFF_KL + boff) = make_uint2(pack_bf2(kk.x - khx, kk.y - khy),
                                                    pack_bf2(kk.z - khz, kk.w - khw));
        float4 v = V4[idx];
        float vhx = bf_hi_f(v.x), vhy = bf_hi_f(v.y), vhz = bf_hi_f(v.z), vhw = bf_hi_f(v.w);
        *(uint2*)(smc + OFF_VH + boff) = make_uint2(pack_bf2(v.x, v.y), pack_bf2(v.z, v.w));
        *(uint2*)(smc + OFF_VL + boff) = make_uint2(pack_bf2(v.x - vhx, v.y - vhy),
                                                    pack_bf2(v.z - vhz, v.w - vhw));
    }
    __syncthreads();

    const int row0 = wid * 16;               // warp's 16 M-rows
    const int g    = lane >> 2;               // fragment row within tile
    const int q4   = lane & 3;                 // fragment col quad
    const int R0   = row0 + g;
    const int R1   = R0 + 8;

    // ---- GEMM1: S = Qh*Kh + Qh*Kl + Ql*Kh (128x128x64) ----
    float acc[16][4];
    #pragma unroll
    for (int nt = 0; nt < 16; nt++)
        #pragma unroll
        for (int i = 0; i < 4; i++) acc[nt][i] = 0.f;

    #pragma unroll
    for (int k0 = 0; k0 < 64; k0 += 16) {
        uint32_t ah[4], al[4];
        uint32_t aaddr = sb + OFF_QH + (uint32_t)(row0 + (lane & 15)) * QK_STRIDE
                       + (uint32_t)(k0 + ((lane >> 4) << 3)) * 2;
        ldsm_x4(ah, aaddr);
        ldsm_x4(al, aaddr + (OFF_QL - OFF_QH));
        #pragma unroll
        for (int nt = 0; nt < 16; nt++) {
            uint32_t bh[2], bl[2];
            uint32_t baddr = sb + OFF_KH + (uint32_t)(nt * 8 + (lane & 7)) * QK_STRIDE
                           + (uint32_t)(k0 + (((lane >> 3) & 1) << 3)) * 2;
            ldsm_x2(bh, baddr);
            ldsm_x2(bl, baddr + (OFF_KL - OFF_KH));
            mma_bf16(acc[nt], ah, bh);
            mma_bf16(acc[nt], ah, bl);
            mma_bf16(acc[nt], al, bh);
        }
    }

    // All warps must finish reading Q/K before P overlays them
    __syncthreads();

    // ---- masked softmax in registers (row = quad), exact fp32 ----
    const int* mrow0 = Mask + (size_t)b * TL * TL + R0 * TL + q4 * 2;
    const int* mrow1 = mrow0 + 8 * TL;
    float sum0 = 0.f, sum1 = 0.f;
    #pragma unroll
    for (int nt = 0; nt < 16; nt++) {
        int2 m0 = *(const int2*)(mrow0 + nt * 8);
        int2 m1 = *(const int2*)(mrow1 + nt * 8);
        float w0 = m0.x ? __expf(acc[nt][0] * 0.125f) : 0.f;
        float w1 = m0.y ? __expf(acc[nt][1] * 0.125f) : 0.f;
        float w2 = m1.x ? __expf(acc[nt][2] * 0.125f) : 0.f;
        float w3 = m1.y ? __expf(acc[nt][3] * 0.125f) : 0.f;
        acc[nt][0] = w0; acc[nt][1] = w1; acc[nt][2] = w2; acc[nt][3] = w3;
        sum0 += w0 + w1;
        sum1 += w2 + w3;
    }
    sum0 += __shfl_xor_sync(0xffffffffu, sum0, 1);
    sum0 += __shfl_xor_sync(0xffffffffu, sum0, 2);
    sum1 += __shfl_xor_sync(0xffffffffu, sum1, 1);
    sum1 += __shfl_xor_sync(0xffffffffu, sum1, 2);
    const float inv0 = 1.0f / sum0;
    const float inv1 = 1.0f / sum1;

    // normalize; write attn fp32 direct (32B sectors per quad) + P bf16 hi/lo to smem
    {
        float* attn = out + OUT_ATTN_OFF + (long long)cta * (TL * TL);
        float* a0 = attn + R0 * TL + q4 * 2;
        float* a1 = attn + R1 * TL + q4 * 2;
        uint32_t p0 = sb + OFF_PH + (uint32_t)R0 * P_STRIDE + (uint32_t)q4 * 4;
        uint32_t p1 = sb + OFF_PH + (uint32_t)R1 * P_STRIDE + (uint32_t)q4 * 4;
        #pragma unroll
        for (int nt = 0; nt < 16; nt++) {
            float w0 = acc[nt][0] * inv0;
            float w1 = acc[nt][1] * inv0;
            float w2 = acc[nt][2] * inv1;
            float w3 = acc[nt][3] * inv1;
            *(float2*)(a0 + nt * 8) = make_float2(w0, w1);
            *(float2*)(a1 + nt * 8) = make_float2(w2, w3);
            uint32_t h01 = pack_bf2(w0, w1), h23 = pack_bf2(w2, w3);
            float r0 = w0 - bf_hi_f(w0), r1 = w1 - bf_hi_f(w1);
            float r2 = w2 - bf_hi_f(w2), r3 = w3 - bf_hi_f(w3);
            uint32_t off = (uint32_t)nt * 16u;
            *(uint32_t*)(smc + (p0 - sb) + off) = h01;
            *(uint32_t*)(smc + (p1 - sb) + off) = h23;
            *(uint32_t*)(smc + (p0 - sb) + (OFF_PL - OFF_PH) + off) = pack_bf2(r0, r1);
            *(uint32_t*)(smc + (p1 - sb) + (OFF_PL - OFF_PH) + off) = pack_bf2(r2, r3);
        }
    }
    __syncwarp();   // warp w reads only its own 16 P rows below

    // ---- GEMM2: O = Ph*Vh + Ph*Vl + Pl*Vh (128x64x128), V frags via ldmatrix.trans ----
    float oacc[8][4];
    #pragma unroll
    for (int nt = 0; nt < 8; nt++)
        #pragma unroll
        for (int i = 0; i < 4; i++) oacc[nt][i] = 0.f;

    #pragma unroll
    for (int j0 = 0; j0 < 128; j0 += 16) {
        uint32_t ph[4], pl[4];
        uint32_t aaddr = sb + OFF_PH + (uint32_t)(row0 + (lane & 15)) * P_STRIDE
                       + (uint32_t)(j0 + ((lane >> 4) << 3)) * 2;
        ldsm_x4(ph, aaddr);
        ldsm_x4(pl, aaddr + (OFF_PL - OFF_PH));
        #pragma unroll
        for (int nt = 0; nt < 8; nt++) {
            uint32_t bh[2], bl[2];
            uint32_t baddr = sb + OFF_VH + (uint32_t)(j0 + (lane & 15)) * QK_STRIDE
                           + (uint32_t)(nt * 8) * 2;
            ldsm_x2t(bh, baddr);
            ldsm_x2t(bl, baddr + (OFF_VL - OFF_VH));
            mma_bf16(oacc[nt], ph, bh);
            mma_bf16(oacc[nt], ph, bl);
            mma_bf16(oacc[nt], pl, bh);
        }
    }

    // ---- write O fp32 direct from accumulators (32B sectors per quad) ----
    {
        float* og = out + (long long)cta * (TL * TD);
        float* o0 = og + R0 * TD + q4 * 2;
        float* o1 = og + R1 * TD + q4 * 2;
        #pragma unroll
        for (int nt = 0; nt < 8; nt++) {
            *(float2*)(o0 + nt * 8) = make_float2(oacc[nt][0], oacc[nt][1]);
            *(float2*)(o1 + nt * 8) = make_float2(oacc[nt][2], oacc[nt][3]);
        }
    }
}

extern "C" void kernel_launch(void* const* d_in, const int* in_sizes, int n_in,
                              void* d_out, int out_size)
{
    const float* Q  = (const float*)d_in[0];
    const float* K  = (const float*)d_in[1];
    const float* V  = (const float*)d_in[2];
    const int*   Mk = (const int*)d_in[3];
    float* out = (float*)d_out;

    cudaFuncSetAttribute(isa_hmma_kernel, cudaFuncAttributeMaxDynamicSharedMemorySize, SMEM_BYTES);
    isa_hmma_kernel<<<TB * TH * TB, 256, SMEM_BYTES>>>(Q, K, V, Mk, out);
}